// round 6
// baseline (speedup 1.0000x reference)
#include <cuda_runtime.h>

// Problem constants
#define NB 4
#define NC 8
#define NF 512
#define NT 1000
#define NPAIR 36   // upper triangle incl diagonal of 8x8

// Scratch: per-(b,f) 8x8 complex filter G[m*8+c] = conj(W[c][m])
__device__ float2 g_G[NB * NF * 64];

static __device__ __forceinline__ float2 cmul(float2 a, float2 b) {
    return make_float2(a.x * b.x - a.y * b.y, a.x * b.y + a.y * b.x);
}

static __device__ __forceinline__ float warp_reduce(float v) {
    #pragma unroll
    for (int o = 16; o; o >>= 1) v += __shfl_down_sync(0xffffffffu, v, o);
    return v;
}

// PSD accumulation for pair-group G: rows R0=G and R1=7-G of the upper
// triangle (always 9 pairs); products shared between both mask roles.
// One warp covers all t in [0,1000); x read straight from gmem (L1-cached).
template <int G>
static __device__ __forceinline__ void psd_group_gmem(
    const float* __restrict__ xre, const float* __restrict__ xim, long xbase,
    const float2* msk,
    float* bufr0, float* bufr1, float* bufi0, float* bufi1, int lane)
{
    constexpr int R0 = G;
    constexpr int R1 = 7 - G;
    constexpr int N0 = 8 - G;       // pairs in row R0: (R0, R0..7)
    constexpr int N1 = G + 1;       // pairs in row R1: (R1, R1..7)
    constexpr int NCH = 8 - G;      // channels R0..7 needed
    constexpr int BASE0 = 8 * R0 - (R0 * (R0 - 1)) / 2;
    constexpr int BASE1 = 8 * R1 - (R1 * (R1 - 1)) / 2;

    float aR[2][9], aI[2][9];
    #pragma unroll
    for (int k = 0; k < 9; k++) {
        aR[0][k] = 0.f; aR[1][k] = 0.f; aI[0][k] = 0.f; aI[1][k] = 0.f;
    }

    #pragma unroll 4
    for (int i = 0; i < 32; i++) {
        int t = lane + (i << 5);
        if (t < NT) {
            float2 xv[NCH];
            #pragma unroll
            for (int j = 0; j < NCH; j++) {
                long g = xbase + (long)(R0 + j) * NF * NT + t;
                xv[j] = make_float2(__ldg(xre + g), __ldg(xim + g));
            }
            float2 mm = msk[t];

            float2 a0 = xv[0];                    // x_{R0}
            #pragma unroll
            for (int k = 0; k < N0; k++) {
                float2 bx = xv[k];                // x_{R0+k}
                float pr = a0.x * bx.x + a0.y * bx.y;
                float pi = a0.y * bx.x - a0.x * bx.y;
                aR[0][k] += mm.x * pr; aR[1][k] += mm.y * pr;
                aI[0][k] += mm.x * pi; aI[1][k] += mm.y * pi;
            }
            float2 a1 = xv[R1 - R0];              // x_{R1}
            #pragma unroll
            for (int k = 0; k < N1; k++) {
                float2 bx = xv[(R1 - R0) + k];    // x_{R1+k}
                float pr = a1.x * bx.x + a1.y * bx.y;
                float pi = a1.y * bx.x - a1.x * bx.y;
                aR[0][N0 + k] += mm.x * pr; aR[1][N0 + k] += mm.y * pr;
                aI[0][N0 + k] += mm.x * pi; aI[1][N0 + k] += mm.y * pi;
            }
        }
    }

    #pragma unroll
    for (int k = 0; k < 9; k++) {
        float r0 = warp_reduce(aR[0][k]);
        float r1 = warp_reduce(aR[1][k]);
        float i0 = warp_reduce(aI[0][k]);
        float i1 = warp_reduce(aI[1][k]);
        if (lane == 0) {
            int p = (k < N0) ? (BASE0 + k) : (BASE1 + (k - N0));
            atomicAdd(bufr0 + p, r0);
            atomicAdd(bufr1 + p, r1);
            atomicAdd(bufi0 + p, i0);
            atomicAdd(bufi1 + p, i1);
        }
    }
}

// ---------------------------------------------------------------------------
// Kernel 1: masked PSDs + diag-reg + Gauss-Jordan solve -> G into g_G
// ---------------------------------------------------------------------------
__global__ __launch_bounds__(128)
void psd_solve_kernel(const float* __restrict__ xre, const float* __restrict__ xim,
                      const float* __restrict__ ms,  const float* __restrict__ mn)
{
    __shared__ float2 msk[NT];            // (mask_s, mask_n) normalized
    __shared__ float  bufr[2][NPAIR];
    __shared__ float  bufi[2][NPAIR];
    __shared__ float2 A[64];
    __shared__ float2 Bm[64];
    __shared__ float  sums[2];
    __shared__ float2 pivinv;
    __shared__ float2 winv;

    const int tid = threadIdx.x;
    const int bf  = blockIdx.x;
    const int b   = bf / NF;
    const int f   = bf - b * NF;

    if (tid < NPAIR) {
        bufr[0][tid] = 0.f; bufi[0][tid] = 0.f;
        bufr[1][tid] = 0.f; bufi[1][tid] = 0.f;
    }
    if (tid == 64) { sums[0] = 0.f; sums[1] = 0.f; }

    // load masks (float4), interleave
    const long mbase = ((long)b * NF + f) * NT;
    for (int idx = tid; idx < NT / 4; idx += 128) {
        int t4 = idx * 4;
        float4 s = *reinterpret_cast<const float4*>(ms + mbase + t4);
        float4 n = *reinterpret_cast<const float4*>(mn + mbase + t4);
        float4* dst = reinterpret_cast<float4*>(&msk[t4]);
        dst[0] = make_float4(s.x, n.x, s.y, n.y);
        dst[1] = make_float4(s.z, n.z, s.w, n.w);
    }
    __syncthreads();

    // mask sums + normalize
    {
        float s0 = 0.f, s1 = 0.f;
        for (int t = tid; t < NT; t += 128) { float2 v = msk[t]; s0 += v.x; s1 += v.y; }
        s0 = warp_reduce(s0);
        s1 = warp_reduce(s1);
        if ((tid & 31) == 0) { atomicAdd(&sums[0], s0); atomicAdd(&sums[1], s1); }
    }
    __syncthreads();
    {
        float i0 = 1.f / (sums[0] + 1e-10f);
        float i1 = 1.f / (sums[1] + 1e-10f);
        for (int t = tid; t < NT; t += 128) {
            float2 v = msk[t]; v.x *= i0; v.y *= i1; msk[t] = v;
        }
    }
    __syncthreads();

    // PSD: 4 warps = 4 pair-groups, each over all 1000 t, x from gmem
    {
        const int lane = tid & 31;
        const long xbase = ((long)b * NC) * NF * NT + (long)f * NT;
        switch (tid >> 5) {
            case 0: psd_group_gmem<0>(xre, xim, xbase, msk, bufr[0], bufr[1], bufi[0], bufi[1], lane); break;
            case 1: psd_group_gmem<1>(xre, xim, xbase, msk, bufr[0], bufr[1], bufi[0], bufi[1], lane); break;
            case 2: psd_group_gmem<2>(xre, xim, xbase, msk, bufr[0], bufr[1], bufi[0], bufi[1], lane); break;
            default: psd_group_gmem<3>(xre, xim, xbase, msk, bufr[0], bufr[1], bufi[0], bufi[1], lane); break;
        }
    }
    __syncthreads();

    // diag regularizer d = 1e-6 * tr(psd_n).re + 1e-8
    if (tid == 0) {
        float trn = 0.f;
        #pragma unroll
        for (int c = 0; c < NC; c++) trn += bufr[1][8 * c - (c * (c - 1)) / 2];
        sums[0] = 1e-6f * trn + 1e-8f;
    }
    __syncthreads();

    // build full Hermitian A (psd_n + d I) and Bm (psd_s)
    if (tid < 64) {
        int i = tid >> 3, j = tid & 7;
        int lo = i < j ? i : j;
        int hi = i < j ? j : i;
        int p = 8 * lo - (lo * (lo - 1)) / 2 + (hi - lo);
        float sgn = (i <= j) ? 1.f : -1.f;
        float2 an = make_float2(bufr[1][p], sgn * bufi[1][p]);
        float2 as = make_float2(bufr[0][p], sgn * bufi[0][p]);
        if (i == j) an.x += sums[0];
        A[tid]  = an;
        Bm[tid] = as;
    }
    __syncthreads();

    // Gauss-Jordan: A X = Bm  ->  Bm = X
    {
        int i = tid >> 3, j = tid & 7;
        for (int k = 0; k < 8; k++) {
            if (tid == 0) {
                float2 pv = A[k * 8 + k];
                float d = pv.x * pv.x + pv.y * pv.y;
                pivinv = make_float2(pv.x / d, -pv.y / d);
            }
            __syncthreads();
            if (tid < 64 && i == k) {
                float2 pin = pivinv;
                A[tid]  = cmul(A[tid], pin);
                Bm[tid] = cmul(Bm[tid], pin);
            }
            __syncthreads();
            float2 fct, akj, bkj;
            bool act = (tid < 64) && (i != k);
            if (act) { fct = A[i * 8 + k]; akj = A[k * 8 + j]; bkj = Bm[k * 8 + j]; }
            __syncthreads();
            if (act) {
                float2 a = A[tid], bm = Bm[tid];
                a.x  -= fct.x * akj.x - fct.y * akj.y;
                a.y  -= fct.x * akj.y + fct.y * akj.x;
                bm.x -= fct.x * bkj.x - fct.y * bkj.y;
                bm.y -= fct.x * bkj.y + fct.y * bkj.x;
                A[tid] = a; Bm[tid] = bm;
            }
            __syncthreads();
        }
    }

    // W = X / (beta + tr X); G[m*8+c] = conj(W[c][m]) -> gmem scratch
    if (tid == 0) {
        float2 tr = make_float2(1.0f, 0.0f);  // beta = 1
        #pragma unroll
        for (int c = 0; c < NC; c++) { tr.x += Bm[c * 8 + c].x; tr.y += Bm[c * 8 + c].y; }
        float d = tr.x * tr.x + tr.y * tr.y;
        winv = make_float2(tr.x / d, -tr.y / d);
    }
    __syncthreads();
    if (tid < 64) {
        int i = tid >> 3, j = tid & 7;      // i = c, j = m
        float2 w = cmul(Bm[tid], winv);
        g_G[bf * 64 + j * 8 + i] = make_float2(w.x, -w.y);
    }
}

// ---------------------------------------------------------------------------
// Kernel 2: streaming filter  out[m][t] = sum_c G[m][c] * x[c][t]
// ---------------------------------------------------------------------------
template <bool COMPLEX_OUT>
__global__ __launch_bounds__(256)
void filter_kernel(const float* __restrict__ xre, const float* __restrict__ xim,
                   float* __restrict__ out)
{
    __shared__ float2 Gs[64];
    const int tid = threadIdx.x;
    const int bf  = blockIdx.x;
    const int b   = bf / NF;
    const int f   = bf - b * NF;

    if (tid < 64) Gs[tid] = g_G[bf * 64 + tid];
    __syncthreads();
    if (tid >= 250) return;

    const int t0 = tid * 4;
    const long base = ((long)b * NC) * NF * NT + (long)f * NT;

    if (!COMPLEX_OUT) {
        float acc[8][4] = {};
        #pragma unroll
        for (int c = 0; c < NC; c++) {
            long g = base + (long)c * NF * NT + t0;
            float4 r  = *reinterpret_cast<const float4*>(xre + g);
            float4 im = *reinterpret_cast<const float4*>(xim + g);
            float xr[4] = { r.x, r.y, r.z, r.w };
            float xi[4] = { im.x, im.y, im.z, im.w };
            #pragma unroll
            for (int m = 0; m < 8; m++) {
                float2 gg = Gs[m * 8 + c];
                #pragma unroll
                for (int j = 0; j < 4; j++)
                    acc[m][j] += gg.x * xr[j] - gg.y * xi[j];
            }
        }
        #pragma unroll
        for (int m = 0; m < 8; m++)
            *reinterpret_cast<float4*>(out + base + (long)m * NF * NT + t0) =
                make_float4(acc[m][0], acc[m][1], acc[m][2], acc[m][3]);
    } else {
        #pragma unroll
        for (int mh = 0; mh < 8; mh += 4) {
            float2 acc[4][4];
            #pragma unroll
            for (int mi = 0; mi < 4; mi++)
                #pragma unroll
                for (int j = 0; j < 4; j++) acc[mi][j] = make_float2(0.f, 0.f);
            #pragma unroll
            for (int c = 0; c < NC; c++) {
                long g = base + (long)c * NF * NT + t0;
                float4 r  = *reinterpret_cast<const float4*>(xre + g);
                float4 im = *reinterpret_cast<const float4*>(xim + g);
                float xr[4] = { r.x, r.y, r.z, r.w };
                float xi[4] = { im.x, im.y, im.z, im.w };
                #pragma unroll
                for (int mi = 0; mi < 4; mi++) {
                    float2 gg = Gs[(mh + mi) * 8 + c];
                    #pragma unroll
                    for (int j = 0; j < 4; j++) {
                        acc[mi][j].x += gg.x * xr[j] - gg.y * xi[j];
                        acc[mi][j].y += gg.x * xi[j] + gg.y * xr[j];
                    }
                }
            }
            #pragma unroll
            for (int mi = 0; mi < 4; mi++) {
                float2* op = reinterpret_cast<float2*>(out) + base + (long)(mh + mi) * NF * NT + t0;
                float4* op4 = reinterpret_cast<float4*>(op);
                op4[0] = make_float4(acc[mi][0].x, acc[mi][0].y, acc[mi][1].x, acc[mi][1].y);
                op4[1] = make_float4(acc[mi][2].x, acc[mi][2].y, acc[mi][3].x, acc[mi][3].y);
            }
        }
    }
}

extern "C" void kernel_launch(void* const* d_in, const int* in_sizes, int n_in,
                              void* d_out, int out_size) {
    (void)in_sizes; (void)n_in;
    const float* xre = (const float*)d_in[0];
    const float* xim = (const float*)d_in[1];
    const float* ms  = (const float*)d_in[2];
    const float* mn  = (const float*)d_in[3];
    const int nElem = NB * NC * NF * NT;
    const bool cplx = (out_size >= 2 * nElem);

    psd_solve_kernel<<<NB * NF, 128>>>(xre, xim, ms, mn);
    if (cplx)
        filter_kernel<true><<<NB * NF, 256>>>(xre, xim, (float*)d_out);
    else
        filter_kernel<false><<<NB * NF, 256>>>(xre, xim, (float*)d_out);
}